// round 4
// baseline (speedup 1.0000x reference)
#include <cuda_runtime.h>
#include <cstdint>

typedef unsigned long long ull;

// SimpleGRU — f32x2 packed-FMA persistent kernel.
// lanes = hidden units: thread u (0..255) owns unit u, all 3 gates, all 32
// batches (packed in pairs -> 48 x 64b accumulators). h stored batch-pair-
// packed [k][bp]; W staged per-kb via cp.async; decoder state in registers.

#define HDIM     256
#define THREE_H  768
#define SEQ      64
#define TB       32
#define NTHREADS 256
#define KB       8
#define NKB      32          // 256 / KB
#define WROWF    12          // staged W row: 8 data floats + 4 pad (48B)
#define WSTAGEF  (THREE_H * WROWF)   // 9216 floats per stage buffer
#define UPAD     18          // h row stride in u64 elems (16 data + 2 pad)

// shared-memory byte offsets (all 16B aligned)
#define OFF_HS0  0                  // h buffer 0: 256*18*8 = 36864
#define OFF_HS1  36864              // h buffer 1
#define OFF_WST  73728              // 2 * 36864 W stages (decoder: redu overlay)
#define OFF_RED2 106624             // decoder stage-2: 16*16 u64 = 2048
#define OFF_US   147456             // w_ih col   [768] f32
#define OFF_BIH  150528             // b_ih       [768]
#define OFF_BHH  153600             // b_hh       [768]
#define OFF_WOUT 156672             // w_out      [256]
#define OFF_XS   157696             // x tile     [64][32] f32
#define OFF_OUTS 165888             // decoder outs [32] f32 + b_out
#define SMEM_BYTES 166144

__device__ __forceinline__ ull fma2(ull a, ull b, ull c) {
    ull d; asm("fma.rn.f32x2 %0, %1, %2, %3;" : "=l"(d) : "l"(a), "l"(b), "l"(c));
    return d;
}
__device__ __forceinline__ ull add2(ull a, ull b) {
    ull d; asm("add.rn.f32x2 %0, %1, %2;" : "=l"(d) : "l"(a), "l"(b));
    return d;
}
__device__ __forceinline__ ull mul2(ull a, ull b) {
    ull d; asm("mul.rn.f32x2 %0, %1, %2;" : "=l"(d) : "l"(a), "l"(b));
    return d;
}
__device__ __forceinline__ ull packdup(float x) {
    ull d; asm("mov.b64 %0, {%1, %1};" : "=l"(d) : "f"(x));
    return d;
}
__device__ __forceinline__ ull pack2(float lo, float hi) {
    ull d; asm("mov.b64 %0, {%1, %2};" : "=l"(d) : "f"(lo), "f"(hi));
    return d;
}
__device__ __forceinline__ void unpack2(ull v, float& lo, float& hi) {
    asm("mov.b64 {%0, %1}, %2;" : "=f"(lo), "=f"(hi) : "l"(v));
}
__device__ __forceinline__ float sigf(float v) {
    return __fdividef(1.0f, 1.0f + __expf(-v));
}
__device__ __forceinline__ float tanhf2(float v) {
    return fmaf(2.0f, sigf(2.0f * v), -1.0f);
}

// stage w_hh[:, kb*8 .. kb*8+7] -> [768][WROWF] tile (1536 16B chunks, 6/thread)
__device__ __forceinline__ void stage_kb(const float* __restrict__ w_hh,
                                         float* __restrict__ wst, int kb, int tid) {
#pragma unroll
    for (int r = 0; r < 6; r++) {
        int ch  = tid + r * NTHREADS;     // 0..1535
        int row = ch >> 1;
        int hf  = ch & 1;
        const float* src = w_hh + row * HDIM + kb * KB + hf * 4;
        unsigned d = (unsigned)__cvta_generic_to_shared(wst + row * WROWF + hf * 4);
        asm volatile("cp.async.cg.shared.global [%0], [%1], 16;\n" :: "r"(d), "l"(src));
    }
    asm volatile("cp.async.commit_group;\n");
}

// acc[g][bp] += sum_k w_hh[g*256+tid][k] * (h[k][2bp], h[k][2bp+1])
__device__ __forceinline__ void gemm_step(const float* __restrict__ w_hh,
                                          char* smem, const ull* __restrict__ hs,
                                          int tid, ull (&acc)[3][16]) {
    float* wst = (float*)(smem + OFF_WST);
#pragma unroll
    for (int g = 0; g < 3; g++)
#pragma unroll
        for (int bp = 0; bp < 16; bp++) acc[g][bp] = 0ull;

    stage_kb(w_hh, wst, 0, tid);

#pragma unroll 1
    for (int kb = 0; kb < NKB; kb++) {
        asm volatile("cp.async.wait_group 0;\n");
        __syncthreads();                       // all staged chunks visible
        if (kb + 1 < NKB)
            stage_kb(w_hh, wst + ((kb + 1) & 1) * WSTAGEF, kb + 1, tid);

        const float* w0 = wst + (kb & 1) * WSTAGEF + tid * WROWF;
#pragma unroll
        for (int kc = 0; kc < 2; kc++) {
            float wa[3][4];
            *(float4*)wa[0] = *(const float4*)(w0 + kc * 4);
            *(float4*)wa[1] = *(const float4*)(w0 + 256 * WROWF + kc * 4);
            *(float4*)wa[2] = *(const float4*)(w0 + 512 * WROWF + kc * 4);
#pragma unroll
            for (int kk = 0; kk < 4; kk++) {
                const ull* hrow = hs + (kb * KB + kc * 4 + kk) * UPAD;
                ull h2[16];
#pragma unroll
                for (int q = 0; q < 8; q++) {
                    ulonglong2 t2 = ((const ulonglong2*)hrow)[q];
                    h2[2 * q] = t2.x; h2[2 * q + 1] = t2.y;
                }
                ull w2r = packdup(wa[0][kk]);
                ull w2z = packdup(wa[1][kk]);
                ull w2n = packdup(wa[2][kk]);
#pragma unroll
                for (int bp = 0; bp < 16; bp++) {
                    acc[0][bp] = fma2(w2r, h2[bp], acc[0][bp]);
                    acc[1][bp] = fma2(w2z, h2[bp], acc[1][bp]);
                    acc[2][bp] = fma2(w2n, h2[bp], acc[2][bp]);
                }
            }
        }
    }
}

__global__ __launch_bounds__(NTHREADS, 1)
void gru_kernel(const float* __restrict__ gx, const float* __restrict__ w_ih,
                const float* __restrict__ w_hh, const float* __restrict__ b_ih,
                const float* __restrict__ b_hh, const float* __restrict__ w_out,
                const float* __restrict__ b_out, float* __restrict__ out, int TL) {
    extern __shared__ char smem[];
    const int tid = threadIdx.x;
    const int gb0 = blockIdx.x * TB;

    float* usf   = (float*)(smem + OFF_US);
    float* bihf  = (float*)(smem + OFF_BIH);
    float* bhhf  = (float*)(smem + OFF_BHH);
    float* woutf = (float*)(smem + OFF_WOUT);
    float* xs    = (float*)(smem + OFF_XS);
    float* outsf = (float*)(smem + OFF_OUTS);
    ull*   hsA   = (ull*)(smem + OFF_HS0);
    ull*   hsB   = (ull*)(smem + OFF_HS1);

    // ---- init: params, x tile, zero h buffer A ----
    for (int i = tid; i < THREE_H; i += NTHREADS) {
        usf[i]  = w_ih[i];
        bihf[i] = b_ih[i];
        bhhf[i] = b_hh[i];
    }
    for (int i = tid; i < HDIM; i += NTHREADS) woutf[i] = w_out[i];
    for (int i = tid; i < TB * SEQ; i += NTHREADS) {
        int b = i & 31, t = i >> 5;
        xs[t * 32 + b] = gx[(gb0 + b) * SEQ + t];
    }
#pragma unroll
    for (int q = 0; q < UPAD; q++) hsA[q * 256 + tid] = 0ull;
    if (tid == 0) outsf[32] = b_out[0];
    __syncthreads();

    // hoisted per-unit gate params
    const float u_r = usf[tid], u_z = usf[tid + 256], u_n = usf[tid + 512];
    const float bihr = bihf[tid], bihz = bihf[tid + 256], bihn = bihf[tid + 512];
    const float bhhr = bhhf[tid], bhhz = bhhf[tid + 256], bhhn = bhhf[tid + 512];
    const float ebr = bihr + bhhr, ebz = bihz + bhhz;

    ull acc[3][16];

    // ---- encoder: 64 steps ----
#pragma unroll 1
    for (int t = 0; t < SEQ; t++) {
        const ull* hrd = (t & 1) ? hsB : hsA;
        ull*       hwr = (t & 1) ? hsA : hsB;
        gemm_step(w_hh, smem, hrd, tid, acc);

        const ulonglong2* hold = (const ulonglong2*)(hrd + tid * UPAD);
        ulonglong2*       hdst = (ulonglong2*)(hwr + tid * UPAD);
        const float*      xrow = xs + t * 32;
#pragma unroll
        for (int q = 0; q < 8; q++) {
            ulonglong2 ho = hold[q];
            ulonglong2 st;
#pragma unroll
            for (int e2 = 0; e2 < 2; e2++) {
                int bp = 2 * q + e2;
                float ar0, ar1, az0, az1, an0, an1, h0, h1;
                unpack2(acc[0][bp], ar0, ar1);
                unpack2(acc[1][bp], az0, az1);
                unpack2(acc[2][bp], an0, an1);
                unpack2(e2 ? ho.y : ho.x, h0, h1);
                float x0 = xrow[2 * bp], x1 = xrow[2 * bp + 1];
                float r0 = sigf(fmaf(x0, u_r, ebr) + ar0);
                float r1 = sigf(fmaf(x1, u_r, ebr) + ar1);
                float z0 = sigf(fmaf(x0, u_z, ebz) + az0);
                float z1 = sigf(fmaf(x1, u_z, ebz) + az1);
                float n0 = tanhf2(fmaf(x0, u_n, bihn) + r0 * (an0 + bhhn));
                float n1 = tanhf2(fmaf(x1, u_n, bihn) + r1 * (an1 + bhhn));
                float hn0 = fmaf(z0, h0 - n0, n0);
                float hn1 = fmaf(z1, h1 - n1, n1);
                if (e2) st.y = pack2(hn0, hn1); else st.x = pack2(hn0, hn1);
            }
            hdst[q] = st;
        }
        // next gemm's first barrier orders these writes before reads
    }
    // hidden lives in hsA (SEQ even)

    // ---- gh_dec = w_hh @ hidden + b_hh (registers) ----
    gemm_step(w_hh, smem, hsA, tid, acc);
    {
        ull br2 = packdup(bhhr), bz2 = packdup(bhhz), bn2 = packdup(bhhn);
#pragma unroll
        for (int bp = 0; bp < 16; bp++) {
            acc[0][bp] = add2(acc[0][bp], br2);
            acc[1][bp] = add2(acc[1][bp], bz2);
            acc[2][bp] = add2(acc[2][bp], bn2);
        }
    }
    // hidden + rolling h_t in registers
    ull hid2[16], ht2[16];
    {
        const ulonglong2* hr = (const ulonglong2*)(hsA + tid * UPAD);
#pragma unroll
        for (int q = 0; q < 8; q++) {
            ulonglong2 v = hr[q];
            hid2[2 * q] = v.x; hid2[2 * q + 1] = v.y;
            ht2[2 * q] = v.x;  ht2[2 * q + 1] = v.y;
        }
    }
    const ull w2o = packdup(woutf[tid]);
    ull* redu = (ull*)(smem + OFF_WST);      // [16][257] overlay on W stages
    ull* red2 = (ull*)(smem + OFF_RED2);     // [16][16]
    __syncthreads();    // W stages fully consumed before redu overlay

    // ---- decoder: TL steps, h_t in registers ----
#pragma unroll 1
    for (int t = 0; t < TL; t++) {
        // stage 1: per-unit products
#pragma unroll
        for (int bp = 0; bp < 16; bp++)
            redu[bp * 257 + tid] = mul2(w2o, ht2[bp]);
        __syncthreads();
        // stage 2: 16-way partial sums
        {
            int bp = tid >> 4, seg = tid & 15;
            ull s = 0ull;
#pragma unroll
            for (int j = 0; j < 16; j++)
                s = add2(s, redu[bp * 257 + seg * 16 + j]);
            red2[bp * 16 + seg] = s;
        }
        __syncthreads();
        // stage 3: final sums + emit
        if (tid < 16) {
            ull s = 0ull;
#pragma unroll
            for (int j = 0; j < 16; j++) s = add2(s, red2[tid * 16 + j]);
            float lo, hi;
            unpack2(s, lo, hi);
            float bo = outsf[32];
            lo += bo; hi += bo;
            outsf[2 * tid] = lo; outsf[2 * tid + 1] = hi;
            out[(gb0 + 2 * tid) * TL + t] = lo;
            out[(gb0 + 2 * tid + 1) * TL + t] = hi;
        }
        __syncthreads();
        // gate update: h_{t+1} = gru_cell(out, hidden), gh fixed in acc
#pragma unroll
        for (int bp = 0; bp < 16; bp++) {
            float ar0, ar1, az0, az1, an0, an1, h0, h1;
            unpack2(acc[0][bp], ar0, ar1);
            unpack2(acc[1][bp], az0, az1);
            unpack2(acc[2][bp], an0, an1);
            unpack2(hid2[bp], h0, h1);
            float x0 = outsf[2 * bp], x1 = outsf[2 * bp + 1];
            float r0 = sigf(fmaf(x0, u_r, bihr) + ar0);
            float r1 = sigf(fmaf(x1, u_r, bihr) + ar1);
            float z0 = sigf(fmaf(x0, u_z, bihz) + az0);
            float z1 = sigf(fmaf(x1, u_z, bihz) + az1);
            float n0 = tanhf2(fmaf(x0, u_n, bihn) + r0 * an0);
            float n1 = tanhf2(fmaf(x1, u_n, bihn) + r1 * an1);
            ht2[bp] = pack2(fmaf(z0, h0 - n0, n0), fmaf(z1, h1 - n1, n1));
        }
    }
}

extern "C" void kernel_launch(void* const* d_in, const int* in_sizes, int n_in,
                              void* d_out, int out_size) {
    const float* x     = (const float*)d_in[0];
    const float* w_ih  = (const float*)d_in[1];
    const float* w_hh  = (const float*)d_in[2];
    const float* b_ih  = (const float*)d_in[3];
    const float* b_hh  = (const float*)d_in[4];
    const float* w_out = (const float*)d_in[5];
    const float* b_out = (const float*)d_in[6];
    float* out = (float*)d_out;

    int B  = in_sizes[0] / SEQ;
    int TL = out_size / B;

    cudaFuncSetAttribute(gru_kernel, cudaFuncAttributeMaxDynamicSharedMemorySize,
                         SMEM_BYTES);
    gru_kernel<<<B / TB, NTHREADS, SMEM_BYTES>>>(x, w_ih, w_hh, b_ih, b_hh,
                                                 w_out, b_out, out, TL);
}